// round 1
// baseline (speedup 1.0000x reference)
#include <cuda_runtime.h>
#include <cuda_bf16.h>

// Problem constants
#define B_     32
#define IN_CH  16
#define OUT_CH 16
#define KK     3
#define DIL    4
#define COND   8
#define T_OUT  65536
#define PADW   (DIL * (KK - 1))      // 8
#define T_IN   (T_OUT + PADW)        // 65544
#define WSZ    (IN_CH * KK * OUT_CH) // 768

// Per-batch hypernet weights, each stored duplicated as float2{w,w} so that a
// single 64-bit shared load produces the packed B operand for fma.rn.f32x2.
__device__ float2 g_w[B_ * WSZ];

// ---------------------------------------------------------------------------
// Kernel 1: hypernetwork.  grid=B_, block=WSZ threads.
// h = leakyrelu(p@W1 + b1, 0.2);  w = h@W2 + b2  (flat j = (i*16+c)*16 + o)
// ---------------------------------------------------------------------------
__global__ void hyper_kernel(const float* __restrict__ p,
                             const float* __restrict__ W1,
                             const float* __restrict__ b1,
                             const float* __restrict__ W2,
                             const float* __restrict__ b2) {
    const int b = blockIdx.x;
    const int j = threadIdx.x;           // 0..767
    __shared__ float h[IN_CH];

    if (j < IN_CH) {
        float s = b1[j];
#pragma unroll
        for (int k = 0; k < COND; k++)
            s += p[b * COND + k] * W1[k * IN_CH + j];
        h[j] = (s > 0.0f) ? s : 0.2f * s;
    }
    __syncthreads();

    float s = b2[j];
#pragma unroll
    for (int c = 0; c < IN_CH; c++)
        s += h[c] * W2[c * WSZ + j];

    g_w[b * WSZ + j] = make_float2(s, s);
}

// ---------------------------------------------------------------------------
// Packed fp32x2 FMA (sm_100+): d = a*b + d per 32-bit half.
// ---------------------------------------------------------------------------
__device__ __forceinline__ void fma2(unsigned long long& d,
                                     unsigned long long a,
                                     unsigned long long b) {
    asm volatile("fma.rn.f32x2 %0, %1, %2, %0;" : "+l"(d) : "l"(a), "l"(b));
}

// ---------------------------------------------------------------------------
// Kernel 2: main conv.
//   grid  = (T_OUT/1024, B_)
//   block = (128, 2): threadIdx.x -> 8 consecutive timesteps each,
//                     threadIdx.y -> which half of the 16 output channels.
// Each thread: load 16-float x window per input channel (covers all 3 dilated
// taps), 96 packed FMAs per channel against smem-broadcast weights.
// ---------------------------------------------------------------------------
__global__ __launch_bounds__(256, 2)
void conv_kernel(const float* __restrict__ x, float* __restrict__ y) {
    const int b  = blockIdx.y;
    const int tx = threadIdx.x;   // 0..127
    const int oh = threadIdx.y;   // 0..1

    __shared__ float2 ws[WSZ];    // 6 KB of duplicated weights for this batch
    {
        const int lt = oh * 128 + tx;
#pragma unroll
        for (int k = lt; k < WSZ; k += 256)
            ws[k] = g_w[b * WSZ + k];
    }
    __syncthreads();

    const int t_base = blockIdx.x * 1024 + tx * 8;   // even, 32B aligned
    const float* xb = x + (b * IN_CH) * T_IN + t_base;

    unsigned long long acc[8][4];
#pragma unroll
    for (int op = 0; op < 8; op++)
#pragma unroll
        for (int j = 0; j < 4; j++)
            acc[op][j] = 0ULL;    // bits of (+0.f, +0.f)

#pragma unroll 1
    for (int c = 0; c < IN_CH; c++) {
        // 16-float window x[b][c][t_base .. t_base+15] as 8 packed pairs.
        const unsigned long long* xp =
            reinterpret_cast<const unsigned long long*>(xb + c * T_IN);
        unsigned long long pk[8];
#pragma unroll
        for (int j = 0; j < 8; j++) pk[j] = xp[j];

#pragma unroll
        for (int i = 0; i < KK; i++) {
            const unsigned long long* wrow =
                reinterpret_cast<const unsigned long long*>(
                    &ws[(i * IN_CH + c) * OUT_CH + oh * 8]);
#pragma unroll
            for (int op = 0; op < 8; op++) {
                const unsigned long long w2 = wrow[op];
                // tap i reads x at t + 8 - 4*i  ->  pack shift (4 - 2*i)
#pragma unroll
                for (int j = 0; j < 4; j++)
                    fma2(acc[op][j], pk[j + 4 - 2 * i], w2);
            }
        }
    }

    // y[b][oh*8+op][t_base + 2j .. +2j+1]
    float* yb = y + (b * OUT_CH + oh * 8) * T_OUT + t_base;
#pragma unroll
    for (int op = 0; op < 8; op++) {
        unsigned long long* yo =
            reinterpret_cast<unsigned long long*>(yb + op * T_OUT);
#pragma unroll
        for (int j = 0; j < 4; j++)
            yo[j] = acc[op][j];
    }
}

// ---------------------------------------------------------------------------
extern "C" void kernel_launch(void* const* d_in, const int* in_sizes, int n_in,
                              void* d_out, int out_size) {
    const float* x  = (const float*)d_in[0];
    const float* p  = (const float*)d_in[1];
    const float* W1 = (const float*)d_in[2];
    const float* b1 = (const float*)d_in[3];
    const float* W2 = (const float*)d_in[4];
    const float* b2 = (const float*)d_in[5];
    float* y = (float*)d_out;

    hyper_kernel<<<B_, WSZ>>>(p, W1, b1, W2, b2);

    dim3 grid(T_OUT / 1024, B_);
    dim3 block(128, 2);
    conv_kernel<<<grid, block>>>(x, y);
}

// round 2
// speedup vs baseline: 1.1959x; 1.1959x over previous
#include <cuda_runtime.h>
#include <cuda_bf16.h>

// Problem constants
#define B_     32
#define IN_CH  16
#define OUT_CH 16
#define KK     3
#define DIL    4
#define COND   8
#define T_OUT  65536
#define PADW   (DIL * (KK - 1))      // 8
#define T_IN   (T_OUT + PADW)        // 65544
#define WSZ    (IN_CH * KK * OUT_CH) // 768

// Per-batch hypernet weights, duplicated as {w,w} packed in 64 bits so one
// load yields the packed B operand of fma.rn.f32x2. 16B-aligned for LDS.128.
__device__ ulonglong2 g_w[B_ * WSZ / 2];

// ---------------------------------------------------------------------------
// Kernel 1: hypernetwork.  grid=B_, block=WSZ threads.
// ---------------------------------------------------------------------------
__global__ void hyper_kernel(const float* __restrict__ p,
                             const float* __restrict__ W1,
                             const float* __restrict__ b1,
                             const float* __restrict__ W2,
                             const float* __restrict__ b2) {
    const int b = blockIdx.x;
    const int j = threadIdx.x;           // 0..767
    __shared__ float h[IN_CH];

    if (j < IN_CH) {
        float s = b1[j];
#pragma unroll
        for (int k = 0; k < COND; k++)
            s += p[b * COND + k] * W1[k * IN_CH + j];
        h[j] = (s > 0.0f) ? s : 0.2f * s;
    }
    __syncthreads();

    float s = b2[j];
#pragma unroll
    for (int c = 0; c < IN_CH; c++)
        s += h[c] * W2[c * WSZ + j];

    float2* w2out = reinterpret_cast<float2*>(g_w);
    w2out[b * WSZ + j] = make_float2(s, s);
}

// ---------------------------------------------------------------------------
// Packed fp32x2 FMA (sm_100+): d = a*b + d per 32-bit half.
// ---------------------------------------------------------------------------
__device__ __forceinline__ void fma2(unsigned long long& d,
                                     unsigned long long a,
                                     unsigned long long b) {
    asm volatile("fma.rn.f32x2 %0, %1, %2, %0;" : "+l"(d) : "l"(a), "l"(b));
}

// ---------------------------------------------------------------------------
// Kernel 2: main conv.
//   grid  = (T_OUT/1024, B_)   -> each block: 1024 timesteps (512 pairs)
//   block = (128, 2): tx -> 4 STRIDED output pairs  p = tile*512 + tx + 128*j
//                     ty -> which half of the 16 output channels.
// Lane stride is one pair (8B) -> every LDG.64 / STG.64 is fully coalesced
// (256B per warp instruction = 2 wavefronts). The 3 dilated taps per pair
// overlap within the warp's own 256B footprint -> L1 hits, DRAM traffic 1x.
// ---------------------------------------------------------------------------
__global__ __launch_bounds__(256, 2)
void conv_kernel(const float* __restrict__ x, float* __restrict__ y) {
    const int b  = blockIdx.y;
    const int tx = threadIdx.x;   // 0..127
    const int oh = threadIdx.y;   // 0..1

    // 6KB of duplicated weights for this batch: ws[(i*16+c)*16 + o] (as u64)
    __shared__ ulonglong2 ws[WSZ / 2];
    {
        const int lt = oh * 128 + tx;          // 0..255
#pragma unroll
        for (int k = lt; k < WSZ / 2; k += 256)
            ws[k] = g_w[b * (WSZ / 2) + k];
    }
    __syncthreads();

    const int p0 = blockIdx.x * 512 + tx;      // base pair index (u64 units)
    const unsigned long long* xb =
        reinterpret_cast<const unsigned long long*>(x + (b * IN_CH) * T_IN) + p0;
    const int rowp = T_IN / 2;                 // 32772 pairs per channel row

    unsigned long long acc[4][8];              // [pair j][out ch within half]
#pragma unroll
    for (int j = 0; j < 4; j++)
#pragma unroll
        for (int op = 0; op < 8; op++)
            acc[j][op] = 0ULL;

#pragma unroll 1
    for (int c = 0; c < IN_CH; c++) {
        const unsigned long long* xc = xb + c * rowp;

        // 12 coalesced LDG.64, hoisted for MLP.
        // tap i reads x pair (p + 4 - 2*i): i=0 -> +4, i=1 -> +2, i=2 -> +0
        unsigned long long xv[4][3];
#pragma unroll
        for (int j = 0; j < 4; j++)
#pragma unroll
            for (int i = 0; i < 3; i++)
                xv[j][i] = xc[128 * j + 4 - 2 * i];

        const ulonglong2* wrow =
            &ws[((0 * IN_CH + c) * OUT_CH + oh * 8) / 2];  // 4 u64x2 per tap
#pragma unroll
        for (int i = 0; i < 3; i++) {
            const ulonglong2* wt = wrow + i * (IN_CH * OUT_CH / 2);
#pragma unroll
            for (int m = 0; m < 4; m++) {
                const ulonglong2 w = wt[m];    // ops 2m, 2m+1 (broadcast LDS)
#pragma unroll
                for (int j = 0; j < 4; j++) {
                    fma2(acc[j][2 * m + 0], xv[j][i], w.x);
                    fma2(acc[j][2 * m + 1], xv[j][i], w.y);
                }
            }
        }
    }

    // Store: y[b][oh*8+op][2*(p0+128j) .. +1], coalesced STG.64
    unsigned long long* yb =
        reinterpret_cast<unsigned long long*>(y + (b * OUT_CH + oh * 8) * T_OUT) + p0;
    const int yrowp = T_OUT / 2;               // 32768 pairs per output row
#pragma unroll
    for (int op = 0; op < 8; op++) {
        unsigned long long* yo = yb + op * yrowp;
#pragma unroll
        for (int j = 0; j < 4; j++)
            yo[128 * j] = acc[j][op];
    }
}

// ---------------------------------------------------------------------------
extern "C" void kernel_launch(void* const* d_in, const int* in_sizes, int n_in,
                              void* d_out, int out_size) {
    const float* x  = (const float*)d_in[0];
    const float* p  = (const float*)d_in[1];
    const float* W1 = (const float*)d_in[2];
    const float* b1 = (const float*)d_in[3];
    const float* W2 = (const float*)d_in[4];
    const float* b2 = (const float*)d_in[5];
    float* y = (float*)d_out;

    hyper_kernel<<<B_, WSZ>>>(p, W1, b1, W2, b2);

    dim3 grid(T_OUT / 1024, B_);
    dim3 block(128, 2);
    conv_kernel<<<grid, block>>>(x, y);
}

// round 3
// speedup vs baseline: 1.6903x; 1.4134x over previous
#include <cuda_runtime.h>
#include <cuda_bf16.h>
#include <cstdint>

// Problem constants
#define B_     32
#define IN_CH  16
#define OUT_CH 16
#define KK     3
#define DIL    4
#define COND   8
#define T_OUT  65536
#define PADW   (DIL * (KK - 1))      // 8
#define T_IN   (T_OUT + PADW)        // 65544
#define WSZ    (IN_CH * KK * OUT_CH) // 768

// Pipeline geometry: 64 tiles of 1024 timesteps per batch.
#define TILE_T   1024
#define TILE_P   (TILE_T / 2)        // 512 pairs
#define ROW_P    516                 // pairs copied per channel (512 + 4 tap pad)
#define ROW_PAD  520                 // smem row stride in u64 (16B aligned)
#define ROW_BYTES (ROW_P * 8)        // 4128, multiple of 16
#define CPS      2                   // channels per pipeline stage
#define NSTAGES  (IN_CH / CPS)       // 8
#define NBUF     3                   // triple buffer

// Per-batch hypernet weights, duplicated as {w,w} in 64 bits so one shared
// load yields the packed B operand of fma.rn.f32x2.
__device__ ulonglong2 g_w[B_ * WSZ / 2];

// ---------------------------------------------------------------------------
// Kernel 1: hypernetwork.  grid=B_, block=WSZ threads.
// ---------------------------------------------------------------------------
__global__ void hyper_kernel(const float* __restrict__ p,
                             const float* __restrict__ W1,
                             const float* __restrict__ b1,
                             const float* __restrict__ W2,
                             const float* __restrict__ b2) {
    const int b = blockIdx.x;
    const int j = threadIdx.x;           // 0..767
    __shared__ float h[IN_CH];

    if (j < IN_CH) {
        float s = b1[j];
#pragma unroll
        for (int k = 0; k < COND; k++)
            s += p[b * COND + k] * W1[k * IN_CH + j];
        h[j] = (s > 0.0f) ? s : 0.2f * s;
    }
    __syncthreads();

    float s = b2[j];
#pragma unroll
    for (int c = 0; c < IN_CH; c++)
        s += h[c] * W2[c * WSZ + j];

    float2* w2out = reinterpret_cast<float2*>(g_w);
    w2out[b * WSZ + j] = make_float2(s, s);
}

// ---------------------------------------------------------------------------
// PTX helpers
// ---------------------------------------------------------------------------
__device__ __forceinline__ void fma2(unsigned long long& d,
                                     unsigned long long a,
                                     unsigned long long b) {
    asm volatile("fma.rn.f32x2 %0, %1, %2, %0;" : "+l"(d) : "l"(a), "l"(b));
}

__device__ __forceinline__ uint32_t smem_u32(const void* ptr) {
    uint32_t a;
    asm("{ .reg .u64 t; cvta.to.shared.u64 t, %1; cvt.u32.u64 %0, t; }"
        : "=r"(a) : "l"(ptr));
    return a;
}

__device__ __forceinline__ void mbar_init(uint32_t mbar, uint32_t count) {
    asm volatile("mbarrier.init.shared.b64 [%0], %1;" :: "r"(mbar), "r"(count)
                 : "memory");
}

__device__ __forceinline__ void mbar_expect_tx(uint32_t mbar, uint32_t bytes) {
    asm volatile("mbarrier.arrive.expect_tx.shared.b64 _, [%0], %1;"
                 :: "r"(mbar), "r"(bytes) : "memory");
}

__device__ __forceinline__ void bulk_g2s(uint32_t dst, const void* src,
                                         uint32_t bytes, uint32_t mbar) {
    asm volatile(
        "cp.async.bulk.shared::cta.global.mbarrier::complete_tx::bytes "
        "[%0], [%1], %2, [%3];"
        :: "r"(dst), "l"(src), "r"(bytes), "r"(mbar) : "memory");
}

__device__ __forceinline__ void mbar_wait(uint32_t mbar, uint32_t parity) {
    asm volatile(
        "{\n\t"
        ".reg .pred P;\n\t"
        "WAIT_%=:\n\t"
        "mbarrier.try_wait.parity.acquire.cta.shared::cta.b64 P, [%0], %1, 0x989680;\n\t"
        "@P bra.uni DONE_%=;\n\t"
        "bra.uni WAIT_%=;\n\t"
        "DONE_%=:\n\t"
        "}"
        :: "r"(mbar), "r"(parity) : "memory");
}

// ---------------------------------------------------------------------------
// Kernel 2: main conv with cp.async.bulk triple-buffered smem pipeline.
//   grid  = (64, 32), block = (128, 2)
//   tx -> 4 strided output pairs (stride 128), ty -> half of 16 out channels.
// x flows gmem -> smem via the TMA pipe (no L1 wavefronts, no LDG queue);
// compute reads x via conflict-free LDS.64 and weights via LDS.128 broadcast.
// ---------------------------------------------------------------------------
__global__ __launch_bounds__(256, 2)
void conv_kernel(const float* __restrict__ x, float* __restrict__ y) {
    const int b   = blockIdx.y;
    const int tx  = threadIdx.x;                 // 0..127
    const int oh  = threadIdx.y;                 // 0..1
    const int tid = oh * 128 + tx;               // 0..255

    __shared__ __align__(16) unsigned long long xs[NBUF][CPS][ROW_PAD];
    __shared__ ulonglong2 ws[WSZ / 2];           // 6KB duplicated weights
    __shared__ __align__(8) unsigned long long mbar_store[NBUF];

    // Cooperative weight load (visible after the init __syncthreads).
#pragma unroll
    for (int k = tid; k < WSZ / 2; k += 256)
        ws[k] = g_w[b * (WSZ / 2) + k];

    const uint32_t mbar0 = smem_u32(&mbar_store[0]);
    if (tid == 0) {
#pragma unroll
        for (int i = 0; i < NBUF; i++)
            mbar_init(mbar0 + 8u * i, 1);
    }
    __syncthreads();

    // Per-channel gmem source rows for this tile.
    const float* xbase = x + (size_t)(b * IN_CH) * T_IN + blockIdx.x * TILE_T;

    // Prologue: issue stages 0 and 1.
    if (tid == 0) {
#pragma unroll
        for (int s = 0; s < 2; s++) {
            const uint32_t mb = mbar0 + 8u * s;
            mbar_expect_tx(mb, CPS * ROW_BYTES);
#pragma unroll
            for (int r = 0; r < CPS; r++)
                bulk_g2s(smem_u32(&xs[s][r][0]),
                         xbase + (size_t)(s * CPS + r) * T_IN, ROW_BYTES, mb);
        }
    }

    unsigned long long acc[4][8];                // [pair j][out ch in half]
#pragma unroll
    for (int j = 0; j < 4; j++)
#pragma unroll
        for (int op = 0; op < 8; op++)
            acc[j][op] = 0ULL;

#pragma unroll 1
    for (int s = 0; s < NSTAGES; s++) {
        const int buf = s % NBUF;
        mbar_wait(mbar0 + 8u * buf, (s / NBUF) & 1);
        __syncthreads();   // all threads done with stage s-1 -> its buffer is free

        if (s + 2 < NSTAGES && tid == 0) {
            const int t = s + 2;
            const int tb = t % NBUF;
            const uint32_t mb = mbar0 + 8u * tb;
            mbar_expect_tx(mb, CPS * ROW_BYTES);
#pragma unroll
            for (int r = 0; r < CPS; r++)
                bulk_g2s(smem_u32(&xs[tb][r][0]),
                         xbase + (size_t)(t * CPS + r) * T_IN, ROW_BYTES, mb);
        }

#pragma unroll
        for (int cc = 0; cc < CPS; cc++) {
            const int c = s * CPS + cc;
            const unsigned long long* xr = &xs[buf][cc][tx];

            // 12 conflict-free LDS.64: tap i at pair offset (4 - 2i)
            unsigned long long xv[4][3];
#pragma unroll
            for (int j = 0; j < 4; j++)
#pragma unroll
                for (int i = 0; i < 3; i++)
                    xv[j][i] = xr[128 * j + 4 - 2 * i];

            const ulonglong2* wrow = &ws[(c * OUT_CH + oh * 8) / 2];
#pragma unroll
            for (int i = 0; i < 3; i++) {
                const ulonglong2* wt = wrow + i * (IN_CH * OUT_CH / 2);
#pragma unroll
                for (int m = 0; m < 4; m++) {
                    const ulonglong2 w = wt[m];      // broadcast LDS.128
#pragma unroll
                    for (int j = 0; j < 4; j++) {
                        fma2(acc[j][2 * m + 0], xv[j][i], w.x);
                        fma2(acc[j][2 * m + 1], xv[j][i], w.y);
                    }
                }
            }
        }
    }

    // Store: y[b][oh*8+op][...], coalesced STG.64
    const int p0 = blockIdx.x * TILE_P + tx;
    unsigned long long* yb =
        reinterpret_cast<unsigned long long*>(y + (size_t)(b * OUT_CH + oh * 8) * T_OUT) + p0;
    const int yrowp = T_OUT / 2;
#pragma unroll
    for (int op = 0; op < 8; op++) {
        unsigned long long* yo = yb + op * yrowp;
#pragma unroll
        for (int j = 0; j < 4; j++)
            yo[128 * j] = acc[j][op];
    }
}

// ---------------------------------------------------------------------------
extern "C" void kernel_launch(void* const* d_in, const int* in_sizes, int n_in,
                              void* d_out, int out_size) {
    const float* x  = (const float*)d_in[0];
    const float* p  = (const float*)d_in[1];
    const float* W1 = (const float*)d_in[2];
    const float* b1 = (const float*)d_in[3];
    const float* W2 = (const float*)d_in[4];
    const float* b2 = (const float*)d_in[5];
    float* y = (float*)d_out;

    hyper_kernel<<<B_, WSZ>>>(p, W1, b1, W2, b2);

    dim3 grid(T_OUT / TILE_T, B_);
    dim3 block(128, 2);
    conv_kernel<<<grid, block>>>(x, y);
}